// round 5
// baseline (speedup 1.0000x reference)
#include <cuda_runtime.h>
#include <cstdint>

#define KD     24000   // inner (pooled-over) dimension
#define NCH    32      // feature channels
#define RPW    8       // rows per warp
#define WPC    1       // warps per CTA (fine-grained SM load balance)
#define KB     96      // k-chunk staged in smem (24000 = 250 * 96)
#define KBP    112     // padded row stride: (112/4) mod 8 == 4 -> conflict-free STS
#define NCHUNK (KD / KB)
#define F4L    ((RPW * KB) / (4 * 32))   // float4 loads per lane per chunk = 6

typedef unsigned long long ull;

__device__ __forceinline__ ull pack2(float lo, float hi) {
    ull r;
    asm("mov.b64 %0, {%1, %2};" : "=l"(r) : "f"(lo), "f"(hi));
    return r;
}
__device__ __forceinline__ void unpack2(ull v, float& lo, float& hi) {
    asm("mov.b64 {%0, %1}, %2;" : "=f"(lo), "=f"(hi) : "l"(v));
}
// packed fp32x2 fma: d.lo += a.lo*b.lo ; d.hi += a.hi*b.hi
__device__ __forceinline__ void fma2(ull& d, ull a, ull b) {
    asm("fma.rn.f32x2 %0, %1, %2, %0;" : "+l"(d) : "l"(a), "l"(b));
}
__device__ __forceinline__ void add2(ull& d, ull a) {
    asm("add.rn.f32x2 %0, %0, %1;" : "+l"(d) : "l"(a));
}

__global__ __launch_bounds__(WPC * 32)
void meshpool_kernel(const float* __restrict__ F,   // [KD][NCH]
                     const float* __restrict__ R,   // [M][KD]
                     float* __restrict__ out)       // [M][NCH]
{
    // double-buffered, padded stage: one __syncwarp per chunk;
    // row stride 112 floats keeps STS.128 phases on 8 distinct bank groups
    __shared__ float stage[2][RPW][KBP];

    const int lane = threadIdx.x & 31;
    const int row0 = blockIdx.x * RPW;

    // Staging assignment: 4 lanes per row. lane -> (subrow, quad)
    const int subrow = lane >> 2;    // 0..7
    const int quad   = lane & 3;     // 0..3 ; lane loads float4 at k = quad*4 + j*16

    const float* rptr = R + (size_t)(row0 + subrow) * KD + quad * 4;

    // acc[r] = {sum over even k, sum over odd k} for channel `lane` of row r
    ull acc[RPW];
#pragma unroll
    for (int r = 0; r < RPW; r++) acc[r] = 0ULL;
    // per-lane rowsum partials for row `subrow` (two chains hide lat-4 dependency)
    ull sp0 = 0ULL, sp1 = 0ULL;

    // prologue: prefetch chunk 0 of this warp's 8 rows (evict-first: use-once data,
    // keeps L1 free for the shared F working set)
    float4 buf[F4L];
#pragma unroll
    for (int j = 0; j < F4L; j++)
        buf[j] = __ldcs((const float4*)(rptr + j * 16));

    const float* fbase = F + lane;

    for (int c = 0; c < NCHUNK; c++) {
        float (*st)[KBP] = stage[c & 1];

        // ---- stage chunk c into smem + accumulate rowsum partials ----
#pragma unroll
        for (int j = 0; j < F4L; j++) {
            *(float4*)&st[subrow][quad * 4 + j * 16] = buf[j];
            add2(sp0, pack2(buf[j].x, buf[j].y));
            add2(sp1, pack2(buf[j].z, buf[j].w));
        }

        // ---- prefetch chunk c+1 (streaming) while computing chunk c ----
        if (c + 1 < NCHUNK) {
            const float* rnext = rptr + (size_t)(c + 1) * KB;
#pragma unroll
            for (int j = 0; j < F4L; j++)
                buf[j] = __ldcs((const float4*)(rnext + j * 16));
        }

        __syncwarp();   // staged data visible to all lanes (double buffer: no WAR sync)

        // ---- compute: lane = channel, uniform-broadcast R from smem,
        //      F via L1-resident coalesced LDG (one 128B line per k) ----
        const float* fc = fbase + (size_t)c * KB * NCH;
#pragma unroll
        for (int kk = 0; kk < KB; kk += 4) {
            float f0 = __ldg(fc + (kk + 0) * NCH);
            float f1 = __ldg(fc + (kk + 1) * NCH);
            float f2 = __ldg(fc + (kk + 2) * NCH);
            float f3 = __ldg(fc + (kk + 3) * NCH);
            ull fab = pack2(f0, f1);
            ull fcd = pack2(f2, f3);
#pragma unroll
            for (int r = 0; r < RPW; r++) {
                ulonglong2 rr = *(const ulonglong2*)&st[r][kk];
                fma2(acc[r], rr.x, fab);   // k, k+1
                fma2(acc[r], rr.y, fcd);   // k+2, k+3
            }
        }
    }

    // ---- rowsum reduction: lanes 4r..4r+3 hold partials of row r ----
    float s;
    {
        float lo0, hi0, lo1, hi1;
        unpack2(sp0, lo0, hi0);
        unpack2(sp1, lo1, hi1);
        s = (lo0 + hi0) + (lo1 + hi1);
    }
    s += __shfl_xor_sync(0xffffffffu, s, 1);
    s += __shfl_xor_sync(0xffffffffu, s, 2);

    float sums[RPW];
#pragma unroll
    for (int r = 0; r < RPW; r++)
        sums[r] = __shfl_sync(0xffffffffu, s, r * 4);

    // ---- write normalized output (coalesced, 128B per row) ----
#pragma unroll
    for (int r = 0; r < RPW; r++) {
        float lo, hi;
        unpack2(acc[r], lo, hi);
        out[(size_t)(row0 + r) * NCH + lane] = (lo + hi) / sums[r];
    }
}

extern "C" void kernel_launch(void* const* d_in, const int* in_sizes, int n_in,
                              void* d_out, int out_size) {
    // metadata order: features [24000*32], relationships [12000*24000].
    // Pick by size defensively.
    const float* F;
    const float* R;
    if (in_sizes[0] == KD * NCH) {
        F = (const float*)d_in[0];
        R = (const float*)d_in[1];
    } else {
        F = (const float*)d_in[1];
        R = (const float*)d_in[0];
    }
    float* out = (float*)d_out;

    // Maximize L1 carveout (CTA uses only ~7KB smem): protects the shared F
    // working set (~12KB/chunk x ~16-chunk window) from eviction. Host-side
    // attribute set, not a stream op -> graph-capture safe; idempotent.
    cudaFuncSetAttribute(meshpool_kernel,
                         cudaFuncAttributePreferredSharedMemoryCarveout,
                         cudaSharedmemCarveoutMaxL1);

    const int rows = out_size / NCH;                 // 12000
    const int grid = rows / RPW;                     // 1500

    meshpool_kernel<<<grid, WPC * 32>>>(F, R, out);
}

// round 9
// speedup vs baseline: 15.7483x; 15.7483x over previous
#include <cuda_runtime.h>
#include <cstdint>

#define KD     24000   // inner (pooled-over) dimension
#define NCH    32      // feature channels
#define RPW    8       // rows per warp
#define WPC    1       // warps per CTA (fine-grained SM load balance)
#define KB     96      // k-chunk staged in smem (24000 = 250 * 96)
#define KBP    112     // padded row stride: (112/4) mod 8 == 4 -> conflict-free STS
#define NCHUNK (KD / KB)
#define F4L    ((RPW * KB) / (4 * 32))   // float4 loads per lane per chunk = 6

typedef unsigned long long ull;

__device__ __forceinline__ ull pack2(float lo, float hi) {
    ull r;
    asm("mov.b64 %0, {%1, %2};" : "=l"(r) : "f"(lo), "f"(hi));
    return r;
}
__device__ __forceinline__ void unpack2(ull v, float& lo, float& hi) {
    asm("mov.b64 {%0, %1}, %2;" : "=f"(lo), "=f"(hi) : "l"(v));
}
// packed fp32x2 fma: d.lo += a.lo*b.lo ; d.hi += a.hi*b.hi
__device__ __forceinline__ void fma2(ull& d, ull a, ull b) {
    asm("fma.rn.f32x2 %0, %1, %2, %0;" : "+l"(d) : "l"(a), "l"(b));
}
__device__ __forceinline__ void add2(ull& d, ull a) {
    asm("add.rn.f32x2 %0, %0, %1;" : "+l"(d) : "l"(a));
}

// min 12 CTAs/SM residency hint: 12*32*82 regs = 31.5K << 64K, no spill risk.
__global__ __launch_bounds__(WPC * 32, 12)
void meshpool_kernel(const float* __restrict__ F,   // [KD][NCH]
                     const float* __restrict__ R,   // [M][KD]
                     float* __restrict__ out)       // [M][NCH]
{
    // double-buffered, padded stage: one __syncwarp per chunk;
    // row stride 112 floats keeps STS.128 phases on 8 distinct bank groups
    __shared__ float stage[2][RPW][KBP];

    const int lane = threadIdx.x & 31;
    const int row0 = blockIdx.x * RPW;

    // Staging assignment: 4 lanes per row. lane -> (subrow, quad)
    const int subrow = lane >> 2;    // 0..7
    const int quad   = lane & 3;     // 0..3 ; lane loads float4 at k = quad*4 + j*16

    const float* rptr = R + (size_t)(row0 + subrow) * KD + quad * 4;

    // acc[r] = {sum over even k, sum over odd k} for channel `lane` of row r
    ull acc[RPW];
#pragma unroll
    for (int r = 0; r < RPW; r++) acc[r] = 0ULL;
    // per-lane rowsum partials for row `subrow` (two chains hide lat-4 dependency)
    ull sp0 = 0ULL, sp1 = 0ULL;

    // prologue: prefetch chunk 0 of this warp's 8 rows (evict-first: use-once data,
    // keeps L1 free for the shared F working set)
    float4 buf[F4L];
#pragma unroll
    for (int j = 0; j < F4L; j++)
        buf[j] = __ldcs((const float4*)(rptr + j * 16));

    const float* fbase = F + lane;

    for (int c = 0; c < NCHUNK; c++) {
        float (*st)[KBP] = stage[c & 1];

        // ---- stage chunk c into smem + accumulate rowsum partials ----
#pragma unroll
        for (int j = 0; j < F4L; j++) {
            *(float4*)&st[subrow][quad * 4 + j * 16] = buf[j];
            add2(sp0, pack2(buf[j].x, buf[j].y));
            add2(sp1, pack2(buf[j].z, buf[j].w));
        }

        // ---- prefetch chunk c+1 (streaming) while computing chunk c ----
        if (c + 1 < NCHUNK) {
            const float* rnext = rptr + (size_t)(c + 1) * KB;
#pragma unroll
            for (int j = 0; j < F4L; j++)
                buf[j] = __ldcs((const float4*)(rnext + j * 16));
        }

        __syncwarp();   // staged data visible to all lanes (double buffer: no WAR sync)

        // ---- compute: lane = channel, uniform-broadcast R from smem,
        //      F via L1-resident coalesced LDG (one 128B line per k) ----
        const float* fc = fbase + (size_t)c * KB * NCH;
#pragma unroll
        for (int kk = 0; kk < KB; kk += 4) {
            float f0 = __ldg(fc + (kk + 0) * NCH);
            float f1 = __ldg(fc + (kk + 1) * NCH);
            float f2 = __ldg(fc + (kk + 2) * NCH);
            float f3 = __ldg(fc + (kk + 3) * NCH);
            ull fab = pack2(f0, f1);
            ull fcd = pack2(f2, f3);
#pragma unroll
            for (int r = 0; r < RPW; r++) {
                ulonglong2 rr = *(const ulonglong2*)&st[r][kk];
                fma2(acc[r], rr.x, fab);   // k, k+1
                fma2(acc[r], rr.y, fcd);   // k+2, k+3
            }
        }
    }

    // ---- rowsum reduction: lanes 4r..4r+3 hold partials of row r ----
    float s;
    {
        float lo0, hi0, lo1, hi1;
        unpack2(sp0, lo0, hi0);
        unpack2(sp1, lo1, hi1);
        s = (lo0 + hi0) + (lo1 + hi1);
    }
    s += __shfl_xor_sync(0xffffffffu, s, 1);
    s += __shfl_xor_sync(0xffffffffu, s, 2);

    float sums[RPW];
#pragma unroll
    for (int r = 0; r < RPW; r++)
        sums[r] = __shfl_sync(0xffffffffu, s, r * 4);

    // ---- write normalized output (coalesced, 128B per row) ----
#pragma unroll
    for (int r = 0; r < RPW; r++) {
        float lo, hi;
        unpack2(acc[r], lo, hi);
        out[(size_t)(row0 + r) * NCH + lane] = (lo + hi) / sums[r];
    }
}

extern "C" void kernel_launch(void* const* d_in, const int* in_sizes, int n_in,
                              void* d_out, int out_size) {
    // metadata order: features [24000*32], relationships [12000*24000].
    // Pick by size defensively.
    const float* F;
    const float* R;
    if (in_sizes[0] == KD * NCH) {
        F = (const float*)d_in[0];
        R = (const float*)d_in[1];
    } else {
        F = (const float*)d_in[1];
        R = (const float*)d_in[0];
    }
    float* out = (float*)d_out;

    // NOTE: round-5 post-mortem — the MaxL1 carveout hint capped the SMEM
    // carveout so only ONE 7KB CTA fit per SM (occ=1.6% measured, 12.65ms).
    // Default carveout + __launch_bounds__ minBlocks=12 restore ~10-12
    // co-resident CTAs/SM. Do NOT re-add the carveout hint.

    const int rows = out_size / NCH;                 // 12000
    const int grid = rows / RPW;                     // 1500

    meshpool_kernel<<<grid, WPC * 32>>>(F, R, out);
}